// round 9
// baseline (speedup 1.0000x reference)
#include <cuda_runtime.h>
#include <cstdint>

// BakeAugment: JPEG stage at quality=15 zeroes every quantized DCT coefficient
// (|dctp/q| <= 8/33.3 < 0.5), so apply_jpeg() == constant (0, 0.52914, 0).
// Reference collapses to two INDEPENDENT elementwise streams:
//   inp    = clip( clip(Cc + gauss*0.03, 0,1) + sh_c, 1e-8,1)^0.9   <- gauss only
//   target = clip( clip(x + sh_c,          1e-8,1)^0.9, 0,1)        <- x only
// R1: powf->MUFU. R3: warp-contiguous. R5-R8: all L2 cache-policy hints are
// neutral; steady state = 200MB compulsory traffic @ ~5.7TB/s. R9: shape the
// streams — split the grid so each block touches exactly ONE input array and
// ONE output region (1 read + 1 write stream per SM instead of 4 interleaved),
// improving HBM row locality and cutting per-block register/instruction count.

__device__ __forceinline__ float gamma_clip(float v) {
    v = fminf(fmaxf(v, 1e-8f), 1.0f);
    v = exp2f(0.9f * __log2f(v));       // MUFU.LG2 / FMUL / MUFU.EX2
    return fminf(v, 1.0f);              // >= 0 by construction
}

// 256-bit load / store (keep memory instruction count minimal).
__device__ __forceinline__ void ld8(const float* p, float f[8]) {
    uint64_t r0, r1, r2, r3;
    asm volatile("ld.global.nc.v4.b64 {%0,%1,%2,%3}, [%4];"
                 : "=l"(r0), "=l"(r1), "=l"(r2), "=l"(r3) : "l"(p));
    f[0] = __uint_as_float((uint32_t)r0); f[1] = __uint_as_float((uint32_t)(r0 >> 32));
    f[2] = __uint_as_float((uint32_t)r1); f[3] = __uint_as_float((uint32_t)(r1 >> 32));
    f[4] = __uint_as_float((uint32_t)r2); f[5] = __uint_as_float((uint32_t)(r2 >> 32));
    f[6] = __uint_as_float((uint32_t)r3); f[7] = __uint_as_float((uint32_t)(r3 >> 32));
}

__device__ __forceinline__ void st8(float* p, const float f[8]) {
    uint64_t r0 = (uint64_t)__float_as_uint(f[0]) | ((uint64_t)__float_as_uint(f[1]) << 32);
    uint64_t r1 = (uint64_t)__float_as_uint(f[2]) | ((uint64_t)__float_as_uint(f[3]) << 32);
    uint64_t r2 = (uint64_t)__float_as_uint(f[4]) | ((uint64_t)__float_as_uint(f[5]) << 32);
    uint64_t r3 = (uint64_t)__float_as_uint(f[6]) | ((uint64_t)__float_as_uint(f[7]) << 32);
    asm volatile("st.global.v4.b64 [%0], {%1,%2,%3,%4};"
                 :: "l"(p), "l"(r0), "l"(r1), "l"(r2), "l"(r3) : "memory");
}

#define TPB 256

__global__ void __launch_bounds__(TPB)
bake_kernel(const float* __restrict__ x,
            const float* __restrict__ gauss,
            const float* __restrict__ shift,
            float* __restrict__ out,
            int n,        // floats per output tensor
            int halfGrid) // blocks per stream
{
    bool isInp = blockIdx.x < halfGrid;
    int  blk   = isInp ? blockIdx.x : blockIdx.x - halfGrid;

    int q8   = blk * TPB + threadIdx.x;   // float8 index within the stream
    int base = q8 * 8;                    // float index

    // 262144 floats per channel image = 32768 float8 -> channel uniform per q8.
    int c = (q8 >> 15) % 3;
    float sh = __ldg(&shift[c]) * 0.05f;

    float in8[8], o8[8];
    if (isInp) {
        // inp stream: reads gauss only, writes out[0:n]
        float cc = (c == 1) ? (0.34414f * 0.5f + 0.71414f * 0.5f) : 0.0f;
        ld8(&gauss[base], in8);
#pragma unroll
        for (int i = 0; i < 8; i++)
            o8[i] = gamma_clip(fminf(fmaxf(fmaf(in8[i], 0.03f, cc), 0.0f), 1.0f) + sh);
        st8(&out[base], o8);
    } else {
        // target stream: reads x only, writes out[n:2n]
        ld8(&x[base], in8);
#pragma unroll
        for (int i = 0; i < 8; i++)
            o8[i] = gamma_clip(in8[i] + sh);
        st8(&out[n + base], o8);
    }
}

extern "C" void kernel_launch(void* const* d_in, const int* in_sizes, int n_in,
                              void* d_out, int out_size) {
    // Inputs per setup_inputs() order: x, dither, gauss, shift
    const float* x     = (const float*)d_in[0];
    // d_in[1] (dither) is mathematically unused: the JPEG stage is constant.
    const float* gauss = (const float*)d_in[2];
    const float* shift = (const float*)d_in[3];
    float* out = (float*)d_out;

    int n  = out_size / 2;        // floats per output tensor (inp, target)
    int n8 = n / 8;               // 1,572,864 float8; divisible by TPB
    int halfGrid = n8 / TPB;      // 6144 blocks per stream
    bake_kernel<<<2 * halfGrid, TPB>>>(x, gauss, shift, out, n, halfGrid);
}

// round 10
// speedup vs baseline: 1.0009x; 1.0009x over previous
#include <cuda_runtime.h>

// BakeAugment: JPEG stage at quality=15 zeroes every quantized DCT coefficient
// (|dctp/q| <= 8/33.3 < 0.5), so apply_jpeg() == constant (0, 0.52914, 0).
// Reference collapses to two elementwise streams:
//   inp    = clip( clip(Cc + gauss*0.03, 0,1) + sh_c, 1e-8,1)^0.9  (clip 0..1)
//   target = clip( clip(x + sh_c,          1e-8,1)^0.9, 0,1)
//
// Roofline summary (R1-R9): powf->MUFU removed the compute wall (62->35us);
// after that, every memory-shaping variant (MLP 2/4/8, 128/256-bit, all L2
// evict/wt hints, split vs interleaved streams) measures 34.9-35.6us with DRAM
// at a constant 5.6-5.7 TB/s. Compulsory traffic is 200MB/replay (100 read +
// 100 write, all unique bytes), so 200MB / 5.7TB/s = 35.1us IS the mixed-R/W
// roofline on this chip. This kernel is the best-measured config (R4) with a
// final block-size tune.

__device__ __forceinline__ float gamma_clip(float v) {
    v = fminf(fmaxf(v, 1e-8f), 1.0f);
    v = exp2f(0.9f * __log2f(v));       // MUFU.LG2 / FMUL / MUFU.EX2
    return fminf(v, 1.0f);              // >= 0 by construction
}

#define V   2    // float4 quads per stream per thread
#define TPB 512

__global__ void __launch_bounds__(TPB)
bake_kernel(const float4* __restrict__ x,
            const float4* __restrict__ gauss,
            const float* __restrict__ shift,
            float4* __restrict__ out,
            int n4)  // float4 elements per output tensor
{
    // Block owns a contiguous chunk of V*TPB quads; every memory instruction is
    // warp-contiguous (lane L at chunk + i*TPB + L).
    int chunk = blockIdx.x * (V * TPB);
    int q0    = chunk + threadIdx.x;

    // 65536 quads per channel image; chunk size (1024) divides it, so the whole
    // chunk lies in one channel.
    int c = (chunk >> 16) % 3;
    float cc = (c == 1) ? (0.34414f * 0.5f + 0.71414f * 0.5f) : 0.0f;
    float sh = __ldg(&shift[c]) * 0.05f;

    // Front-batch all 2*V independent loads (MLP = 4).
    float4 g4[V], x4[V];
#pragma unroll
    for (int i = 0; i < V; i++) g4[i] = __ldcs(&gauss[q0 + i * TPB]);
#pragma unroll
    for (int i = 0; i < V; i++) x4[i] = __ldcs(&x[q0 + i * TPB]);

#pragma unroll
    for (int i = 0; i < V; i++) {
        float4 o;
        o.x = gamma_clip(fminf(fmaxf(fmaf(g4[i].x, 0.03f, cc), 0.0f), 1.0f) + sh);
        o.y = gamma_clip(fminf(fmaxf(fmaf(g4[i].y, 0.03f, cc), 0.0f), 1.0f) + sh);
        o.z = gamma_clip(fminf(fmaxf(fmaf(g4[i].z, 0.03f, cc), 0.0f), 1.0f) + sh);
        o.w = gamma_clip(fminf(fmaxf(fmaf(g4[i].w, 0.03f, cc), 0.0f), 1.0f) + sh);
        __stcs(&out[q0 + i * TPB], o);
    }

#pragma unroll
    for (int i = 0; i < V; i++) {
        float4 o;
        o.x = gamma_clip(x4[i].x + sh);
        o.y = gamma_clip(x4[i].y + sh);
        o.z = gamma_clip(x4[i].z + sh);
        o.w = gamma_clip(x4[i].w + sh);
        __stcs(&out[n4 + q0 + i * TPB], o);
    }
}

extern "C" void kernel_launch(void* const* d_in, const int* in_sizes, int n_in,
                              void* d_out, int out_size) {
    // Inputs per setup_inputs() order: x, dither, gauss, shift
    const float4* x     = (const float4*)d_in[0];
    // d_in[1] (dither) is mathematically unused: the JPEG stage is constant.
    const float4* gauss = (const float4*)d_in[2];
    const float*  shift = (const float*)d_in[3];
    float4* out = (float4*)d_out;

    int n  = out_size / 2;     // elements per output tensor (inp, target)
    int n4 = n / 4;            // 3,145,728 quads; divisible by V*TPB = 1024
    int blocks = n4 / (V * TPB);
    bake_kernel<<<blocks, TPB>>>(x, gauss, shift, out, n4);
}